// round 12
// baseline (speedup 1.0000x reference)
#include <cuda_runtime.h>
#include <cuda_fp16.h>
#include <math.h>
#include <float.h>
#include <stdint.h>

#define T_DIM 8192
#define D_DIM 512
#define N_SYN 4
#define NTILE 64                  // 8192 / 128 column tiles
#define TS 128                    // CTA tile M=N
#define KC 64                     // k elems (halves) per smem stage
#define NSTAGE (D_DIM / KC)       // 8
#define LDKH 72                   // padded smem row stride in halves (144B, conflict-free)
#define TILE_H (TS * LDKH)        // halves per tile (9216)
#define STAGE_H (4 * TILE_H)      // AH AL BH BL (36864 halves = 73728 B)
#define EPI_LD 129                // epilogue smem stride (conflict-free row+col scans)

// ---------------------------------------------------------------------------
// Device-global scratch
// ---------------------------------------------------------------------------
__device__ float g_sq[T_DIM];
__device__ int   g_nb[T_DIM * 4];
__device__ __half g_hi[(size_t)T_DIM * D_DIM];    // 8 MB
__device__ __half g_lo[(size_t)T_DIM * D_DIM];    // 8 MB
__device__ float g_pd[(size_t)T_DIM * NTILE * 5]; // per-(row, coltile) top-5 dists
__device__ int   g_pi[(size_t)T_DIM * NTILE * 5]; // ... and indices

// ---------------------------------------------------------------------------
// PTX helpers (baseline sm_80+ -> legal on compute_103)
// ---------------------------------------------------------------------------
__device__ __forceinline__ uint32_t smem_u32(const void* p) {
    uint32_t a;
    asm("{ .reg .u64 t; cvta.to.shared.u64 t, %1; cvt.u32.u64 %0, t; }" : "=r"(a) : "l"(p));
    return a;
}
#define CP_ASYNC_CG(dst_u32, src_ptr) \
    asm volatile("cp.async.cg.shared.global [%0], [%1], 16;" :: "r"(dst_u32), "l"(src_ptr))
#define CP_COMMIT() asm volatile("cp.async.commit_group;" ::: "memory")
#define CP_WAIT(n)  asm volatile("cp.async.wait_group %0;" :: "n"(n) : "memory")

#define MMA_F16(Cp, a, b) \
    asm volatile("mma.sync.aligned.m16n8k16.row.col.f32.f16.f16.f32 " \
        "{%0,%1,%2,%3}, {%4,%5,%6,%7}, {%8,%9}, {%0,%1,%2,%3};" \
        : "+f"((Cp)[0]), "+f"((Cp)[1]), "+f"((Cp)[2]), "+f"((Cp)[3]) \
        : "r"((a)[0]), "r"((a)[1]), "r"((a)[2]), "r"((a)[3]), \
          "r"((b)[0]), "r"((b)[1]))

#define LDSM_X4(r0, r1, r2, r3, addr) \
    asm volatile("ldmatrix.sync.aligned.m8n8.x4.shared.b16 {%0,%1,%2,%3}, [%4];" \
        : "=r"(r0), "=r"(r1), "=r"(r2), "=r"(r3) : "r"(addr))

// ---------------------------------------------------------------------------
// exact top-5 insert, jax.lax.top_k tie semantics (value, then lower index)
// ---------------------------------------------------------------------------
__device__ __forceinline__ bool kless(float d1, int i1, float d2, int i2) {
    return (d1 < d2) || (d1 == d2 && i1 < i2);
}
__device__ __forceinline__ void insert5(float d, int j, float (&d5)[5], int (&i5)[5]) {
    if (kless(d, j, d5[4], i5[4])) {
        d5[4] = d; i5[4] = j;
#pragma unroll
        for (int p = 4; p > 0; p--) {
            if (kless(d5[p], i5[p], d5[p - 1], i5[p - 1])) {
                float td = d5[p]; d5[p] = d5[p - 1]; d5[p - 1] = td;
                int   ti = i5[p]; i5[p] = i5[p - 1]; i5[p - 1] = ti;
            }
        }
    }
}

// ---------------------------------------------------------------------------
// 1) Row squared norms (fp32): one warp per row
// ---------------------------------------------------------------------------
__global__ void sq_kernel(const float* __restrict__ X) {
    int warp = (blockIdx.x * blockDim.x + threadIdx.x) >> 5;
    int lane = threadIdx.x & 31;
    if (warp >= T_DIM) return;
    const float4* xr = reinterpret_cast<const float4*>(X + (size_t)warp * D_DIM);
    float s = 0.f;
#pragma unroll
    for (int c = 0; c < 4; c++) {
        float4 v = xr[lane + c * 32];
        s += v.x * v.x + v.y * v.y + v.z * v.z + v.w * v.w;
    }
#pragma unroll
    for (int o = 16; o > 0; o >>= 1) s += __shfl_down_sync(0xffffffffu, s, o);
    if (lane == 0) g_sq[warp] = s;
}

// ---------------------------------------------------------------------------
// 2) fp16 2-way split: x = hi + lo + r, |r| <= 2^-22 |x|
// ---------------------------------------------------------------------------
__global__ void split_kernel(const float* __restrict__ X) {
    int i = blockIdx.x * blockDim.x + threadIdx.x;   // over T*D/4
    float4 v = reinterpret_cast<const float4*>(X)[i];
    float xs[4] = {v.x, v.y, v.z, v.w};
    unsigned short h[4], l[4];
#pragma unroll
    for (int c = 0; c < 4; c++) {
        __half hh = __float2half_rn(xs[c]);
        float r = xs[c] - __half2float(hh);
        __half ll = __float2half_rn(r);
        h[c] = __half_as_ushort(hh);
        l[c] = __half_as_ushort(ll);
    }
    reinterpret_cast<ushort4*>(g_hi)[i] = make_ushort4(h[0], h[1], h[2], h[3]);
    reinterpret_cast<ushort4*>(g_lo)[i] = make_ushort4(l[0], l[1], l[2], l[3]);
}

// ---------------------------------------------------------------------------
// 3) Fused triangular dist GEMM + per-tile top-5 epilogue.
//    mma.sync fp16 m16n8k16 (dot = hh + hl + lh), 8 warps (4x2).
//    Epilogue: stage d-tile in smem (stride 129), warps 0-3 scan direct rows,
//    warps 4-7 scan mirror rows (columns); exact per-tile top-5 -> g_pd/g_pi.
// ---------------------------------------------------------------------------
__global__ __launch_bounds__(256, 1) void dist_mma_kernel() {
    extern __shared__ __align__(16) __half smh[];
    const int tid = threadIdx.x;
    const int lane = tid & 31, wid = tid >> 5;
    const int warpM = wid & 3;        // m offset *32
    const int warpN = wid >> 2;       // n offset *64
    const int gID = lane >> 2, tig = lane & 3;

    // triangular decode: blockIdx.x -> (bx >= by)
    int t = blockIdx.x;
    int a = (int)((sqrtf(8.0f * (float)t + 1.0f) - 1.0f) * 0.5f);
    while ((a + 1) * (a + 2) / 2 <= t) a++;
    while (a * (a + 1) / 2 > t) a--;
    const int bx = a;
    const int by = t - a * (a + 1) / 2;
    const int rowTile = by * TS;
    const int colTile = bx * TS;

    const uint32_t smbase = smem_u32(smh);

    // ldmatrix per-lane address components (half-element offsets)
    const uint32_t aRow = (uint32_t)(warpM * 32 + (lane & 15));
    const uint32_t aK   = (uint32_t)((lane >> 4) * 8);
    const uint32_t bRow = (uint32_t)(warpN * 64 + ((lane >> 4) & 1) * 8 + (lane & 7));
    const uint32_t bK   = (uint32_t)(((lane >> 3) & 1) * 8);

    float c[2][8][4];
#pragma unroll
    for (int i = 0; i < 2; i++)
#pragma unroll
        for (int j = 0; j < 8; j++)
#pragma unroll
            for (int q = 0; q < 4; q++) c[i][j][q] = 0.f;

    // stage loader: 4 tiles (AH, AL, BH, BL), each 128 rows x 64 halves
    auto issue_stage = [&](int stage, int k0) {
        const __half* gsrc[4] = {g_hi, g_lo, g_hi, g_lo};
        const int    rbase[4] = {rowTile, rowTile, colTile, colTile};
#pragma unroll
        for (int tIdx = 0; tIdx < 4; tIdx++) {
            const __half* src = gsrc[tIdx];
            uint32_t dstBase = smbase + (uint32_t)(stage * STAGE_H + tIdx * TILE_H) * 2u;
#pragma unroll
            for (int q = 0; q < 4; q++) {
                int seg = tid + q * 256;            // 0..1023
                int m = seg >> 3, s = seg & 7;      // row, 16B segment (8 halves)
                uint32_t d = dstBase + (uint32_t)(m * LDKH + s * 8) * 2u;
                const __half* g = src + (size_t)(rbase[tIdx] + m) * D_DIM + k0 + s * 8;
                CP_ASYNC_CG(d, g);
            }
        }
        CP_COMMIT();
    };

    issue_stage(0, 0);

    for (int it = 0; it < NSTAGE; it++) {
        if (it + 1 < NSTAGE) {
            issue_stage((it + 1) & 1, (it + 1) * KC);
            CP_WAIT(1);
        } else {
            CP_WAIT(0);
        }
        __syncthreads();

        const uint32_t AHs = smbase + (uint32_t)((it & 1) * STAGE_H) * 2u;
        const uint32_t ALs = AHs + (uint32_t)TILE_H * 2u;
        const uint32_t BHs = AHs + (uint32_t)(2 * TILE_H) * 2u;
        const uint32_t BLs = AHs + (uint32_t)(3 * TILE_H) * 2u;

#pragma unroll
        for (int kk = 0; kk < 4; kk++) {           // four k16 steps per stage
            const uint32_t kb = (uint32_t)(kk * 16);
            uint32_t ah[2][4], al[2][4], bh[8][2], bl[8][2];
#pragma unroll
            for (int tm = 0; tm < 2; tm++) {
                uint32_t offA = ((aRow + tm * 16u) * LDKH + kb + aK) * 2u;
                LDSM_X4(ah[tm][0], ah[tm][1], ah[tm][2], ah[tm][3], AHs + offA);
                LDSM_X4(al[tm][0], al[tm][1], al[tm][2], al[tm][3], ALs + offA);
            }
#pragma unroll
            for (int tp = 0; tp < 4; tp++) {
                uint32_t offB = ((bRow + tp * 16u) * LDKH + kb + bK) * 2u;
                LDSM_X4(bh[2 * tp][0], bh[2 * tp][1], bh[2 * tp + 1][0], bh[2 * tp + 1][1],
                        BHs + offB);
                LDSM_X4(bl[2 * tp][0], bl[2 * tp][1], bl[2 * tp + 1][0], bl[2 * tp + 1][1],
                        BLs + offB);
            }
#pragma unroll
            for (int tm = 0; tm < 2; tm++)
#pragma unroll
                for (int tn = 0; tn < 8; tn++) {
                    MMA_F16(c[tm][tn], ah[tm], bh[tn]);
                    MMA_F16(c[tm][tn], ah[tm], bl[tn]);
                    MMA_F16(c[tm][tn], al[tm], bh[tn]);
                }
        }
        __syncthreads();
    }

    // ---- Epilogue phase 1: d-tile -> smem (stride EPI_LD, conflict-free scans)
    float* ds = reinterpret_cast<float*>(smh);     // 128*129*4 = 66048 B, fits
#pragma unroll
    for (int tm = 0; tm < 2; tm++) {
        int r0 = warpM * 32 + tm * 16 + gID;       // local row
        float sqr0 = g_sq[rowTile + r0], sqr1 = g_sq[rowTile + r0 + 8];
#pragma unroll
        for (int tn = 0; tn < 8; tn++) {
            int c0 = warpN * 64 + tn * 8 + 2 * tig;    // local col
            float sqc0 = g_sq[colTile + c0], sqc1 = g_sq[colTile + c0 + 1];
            float* C = c[tm][tn];
            ds[r0 * EPI_LD + c0]           = sqrtf(fmaxf(sqr0 + sqc0 - 2.f * C[0], 0.f));
            ds[r0 * EPI_LD + c0 + 1]       = sqrtf(fmaxf(sqr0 + sqc1 - 2.f * C[1], 0.f));
            ds[(r0 + 8) * EPI_LD + c0]     = sqrtf(fmaxf(sqr1 + sqc0 - 2.f * C[2], 0.f));
            ds[(r0 + 8) * EPI_LD + c0 + 1] = sqrtf(fmaxf(sqr1 + sqc1 - 2.f * C[3], 0.f));
        }
    }
    __syncthreads();

    // ---- Epilogue phase 2: per-tile exact top-5. warps 0-3: direct rows;
    //      warps 4-7: mirror rows (columns). Diagonal tiles skip mirror.
    if (tid < 128 || bx != by) {
        float d5[5]; int i5[5];
#pragma unroll
        for (int r = 0; r < 5; r++) { d5[r] = FLT_MAX; i5[r] = 0x7fffffff; }
        int grow;
        size_t base;
        if (tid < 128) {
            const float* rowp = ds + tid * EPI_LD;
            for (int i = 0; i < 128; i++) {
                float d = rowp[i];
                if (d <= d5[4]) insert5(d, colTile + i, d5, i5);
            }
            grow = rowTile + tid;
            base = ((size_t)grow * NTILE + bx) * 5;
        } else {
            int cl = tid - 128;
            for (int r = 0; r < 128; r++) {
                float d = ds[r * EPI_LD + cl];
                if (d <= d5[4]) insert5(d, rowTile + r, d5, i5);
            }
            grow = colTile + cl;
            base = ((size_t)grow * NTILE + by) * 5;
        }
#pragma unroll
        for (int r = 0; r < 5; r++) { g_pd[base + r] = d5[r]; g_pi[base + r] = i5[r]; }
    }
}

// ---------------------------------------------------------------------------
// 4) Merge per-tile top-5 partials: one warp per row over 64*5 entries.
//    Global top-5 of a row is contained in the union of its per-tile top-5s.
// ---------------------------------------------------------------------------
__global__ __launch_bounds__(256) void topk_merge_kernel() {
    __shared__ float sd[8][32][5];
    __shared__ int   si[8][32][5];
    const int wid = threadIdx.x >> 5, lane = threadIdx.x & 31;
    const int row = blockIdx.x * 8 + wid;

    const float* pdr = g_pd + (size_t)row * (NTILE * 5);
    const int*   pir = g_pi + (size_t)row * (NTILE * 5);

    float d5[5]; int i5[5];
#pragma unroll
    for (int r = 0; r < 5; r++) { d5[r] = FLT_MAX; i5[r] = 0x7fffffff; }

    for (int e = lane; e < NTILE * 5; e += 32) {
        float d = pdr[e];
        if (d <= d5[4]) insert5(d, pir[e], d5, i5);
    }
#pragma unroll
    for (int r = 0; r < 5; r++) { sd[wid][lane][r] = d5[r]; si[wid][lane][r] = i5[r]; }
    __syncwarp();

    if (lane == 0) {
        for (int t = 1; t < 32; t++)
#pragma unroll
            for (int r = 0; r < 5; r++)
                insert5(sd[wid][t][r], si[wid][t][r], d5, i5);
        // rank 0 is self; keep ranks 1..4
#pragma unroll
        for (int r = 0; r < 4; r++) g_nb[row * 4 + r] = i5[r + 1];
    }
}

// ---------------------------------------------------------------------------
// 5) Interpolate
// ---------------------------------------------------------------------------
__global__ __launch_bounds__(128) void synth_kernel(const float* __restrict__ X,
                                                    const float* __restrict__ gaps,
                                                    const int* __restrict__ choice,
                                                    float* __restrict__ out) {
    int s = blockIdx.x;
    int i = s >> 2;
    int c = choice[s];
    int sel = g_nb[i * 4 + c];
    float g = gaps[s];

    const float4* base = reinterpret_cast<const float4*>(X + (size_t)i * D_DIM);
    const float4* nb   = reinterpret_cast<const float4*>(X + (size_t)sel * D_DIM);
    float4* o = reinterpret_cast<float4*>(out + (size_t)s * D_DIM);

    int t = threadIdx.x;
    float4 b = base[t], v = nb[t];
    float4 r;
    r.x = fmaf(g, v.x - b.x, b.x);
    r.y = fmaf(g, v.y - b.y, b.y);
    r.z = fmaf(g, v.z - b.z, b.z);
    r.w = fmaf(g, v.w - b.w, b.w);
    o[t] = r;
}

// ---------------------------------------------------------------------------
extern "C" void kernel_launch(void* const* d_in, const int* in_sizes, int n_in,
                              void* d_out, int out_size) {
    const float* X      = (const float*)d_in[0];   // [8192, 512]
    const float* gaps   = (const float*)d_in[1];   // [8192, 4]
    const int*   choice = (const int*)d_in[2];     // [8192, 4]
    float* out = (float*)d_out;                    // [32768, 512]

    const int smem_bytes = 2 * STAGE_H * 2;        // 147456 B (>= epilogue 66048)
    cudaFuncSetAttribute(dist_mma_kernel,
                         cudaFuncAttributeMaxDynamicSharedMemorySize, smem_bytes);

    sq_kernel<<<(T_DIM * 32 + 255) / 256, 256>>>(X);
    split_kernel<<<(T_DIM * D_DIM / 4) / 256, 256>>>(X);
    dist_mma_kernel<<<NTILE * (NTILE + 1) / 2, 256, smem_bytes>>>();
    topk_merge_kernel<<<T_DIM / 8, 256>>>();
    synth_kernel<<<T_DIM * N_SYN, 128>>>(X, gaps, choice, out);
}

// round 14
// speedup vs baseline: 1.6147x; 1.6147x over previous
#include <cuda_runtime.h>
#include <cuda_fp16.h>
#include <math.h>
#include <float.h>
#include <stdint.h>

#define T_DIM 8192
#define D_DIM 512
#define N_SYN 4
#define NTILE 64                  // 8192 / 128 blocks per row
#define TS 128                    // CTA tile M=N
#define KC 64                     // k elems (halves) per smem stage
#define NSTAGE (D_DIM / KC)       // 8
#define LDKH 72                   // padded smem row stride in halves (144B, conflict-free)
#define TILE_H (TS * LDKH)        // halves per tile (9216)
#define STAGE_H (4 * TILE_H)      // AH AL BH BL (36864 halves = 73728 B)

// ---------------------------------------------------------------------------
// Device-global scratch
// ---------------------------------------------------------------------------
__device__ float g_sq[T_DIM];
__device__ float g_dist[(size_t)T_DIM * T_DIM];   // 256 MB
__device__ float g_bmin[(size_t)T_DIM * NTILE];   // 2 MB per-(row, 128-block) min
__device__ int   g_nb[T_DIM * 4];
__device__ __half g_hi[(size_t)T_DIM * D_DIM];    // 8 MB
__device__ __half g_lo[(size_t)T_DIM * D_DIM];    // 8 MB

// ---------------------------------------------------------------------------
// PTX helpers (baseline sm_80+ -> legal on compute_103)
// ---------------------------------------------------------------------------
__device__ __forceinline__ uint32_t smem_u32(const void* p) {
    uint32_t a;
    asm("{ .reg .u64 t; cvta.to.shared.u64 t, %1; cvt.u32.u64 %0, t; }" : "=r"(a) : "l"(p));
    return a;
}
#define CP_ASYNC_CG(dst_u32, src_ptr) \
    asm volatile("cp.async.cg.shared.global [%0], [%1], 16;" :: "r"(dst_u32), "l"(src_ptr))
#define CP_COMMIT() asm volatile("cp.async.commit_group;" ::: "memory")
#define CP_WAIT(n)  asm volatile("cp.async.wait_group %0;" :: "n"(n) : "memory")

#define MMA_F16(Cp, a, b) \
    asm volatile("mma.sync.aligned.m16n8k16.row.col.f32.f16.f16.f32 " \
        "{%0,%1,%2,%3}, {%4,%5,%6,%7}, {%8,%9}, {%0,%1,%2,%3};" \
        : "+f"((Cp)[0]), "+f"((Cp)[1]), "+f"((Cp)[2]), "+f"((Cp)[3]) \
        : "r"((a)[0]), "r"((a)[1]), "r"((a)[2]), "r"((a)[3]), \
          "r"((b)[0]), "r"((b)[1]))

#define LDSM_X4(r0, r1, r2, r3, addr) \
    asm volatile("ldmatrix.sync.aligned.m8n8.x4.shared.b16 {%0,%1,%2,%3}, [%4];" \
        : "=r"(r0), "=r"(r1), "=r"(r2), "=r"(r3) : "r"(addr))

// ---------------------------------------------------------------------------
// exact top-5 insert, jax.lax.top_k tie semantics (value, then lower index)
// ---------------------------------------------------------------------------
__device__ __forceinline__ bool kless(float d1, int i1, float d2, int i2) {
    return (d1 < d2) || (d1 == d2 && i1 < i2);
}
__device__ __forceinline__ void insert5(float d, int j, float (&d5)[5], int (&i5)[5]) {
    if (kless(d, j, d5[4], i5[4])) {
        d5[4] = d; i5[4] = j;
#pragma unroll
        for (int p = 4; p > 0; p--) {
            if (kless(d5[p], i5[p], d5[p - 1], i5[p - 1])) {
                float td = d5[p]; d5[p] = d5[p - 1]; d5[p - 1] = td;
                int   ti = i5[p]; i5[p] = i5[p - 1]; i5[p - 1] = ti;
            }
        }
    }
}

// ---------------------------------------------------------------------------
// 1) Row squared norms (fp32): one warp per row
// ---------------------------------------------------------------------------
__global__ void sq_kernel(const float* __restrict__ X) {
    int warp = (blockIdx.x * blockDim.x + threadIdx.x) >> 5;
    int lane = threadIdx.x & 31;
    if (warp >= T_DIM) return;
    const float4* xr = reinterpret_cast<const float4*>(X + (size_t)warp * D_DIM);
    float s = 0.f;
#pragma unroll
    for (int c = 0; c < 4; c++) {
        float4 v = xr[lane + c * 32];
        s += v.x * v.x + v.y * v.y + v.z * v.z + v.w * v.w;
    }
#pragma unroll
    for (int o = 16; o > 0; o >>= 1) s += __shfl_down_sync(0xffffffffu, s, o);
    if (lane == 0) g_sq[warp] = s;
}

// ---------------------------------------------------------------------------
// 2) fp16 2-way split: x = hi + lo + r, |r| <= 2^-22 |x|
// ---------------------------------------------------------------------------
__global__ void split_kernel(const float* __restrict__ X) {
    int i = blockIdx.x * blockDim.x + threadIdx.x;   // over T*D/4
    float4 v = reinterpret_cast<const float4*>(X)[i];
    float xs[4] = {v.x, v.y, v.z, v.w};
    unsigned short h[4], l[4];
#pragma unroll
    for (int c = 0; c < 4; c++) {
        __half hh = __float2half_rn(xs[c]);
        float r = xs[c] - __half2float(hh);
        __half ll = __float2half_rn(r);
        h[c] = __half_as_ushort(hh);
        l[c] = __half_as_ushort(ll);
    }
    reinterpret_cast<ushort4*>(g_hi)[i] = make_ushort4(h[0], h[1], h[2], h[3]);
    reinterpret_cast<ushort4*>(g_lo)[i] = make_ushort4(l[0], l[1], l[2], l[3]);
}

// ---------------------------------------------------------------------------
// 3) Triangular dist GEMM (mma.sync fp16, dot = hh + hl + lh) with dist
//    stores (direct + mirror) PLUS cheap per-(row, tile) block-min reduction.
// ---------------------------------------------------------------------------
__global__ __launch_bounds__(256, 1) void dist_mma_kernel() {
    extern __shared__ __align__(16) __half smh[];
    const int tid = threadIdx.x;
    const int lane = tid & 31, wid = tid >> 5;
    const int warpM = wid & 3;        // m offset *32
    const int warpN = wid >> 2;       // n offset *64
    const int gID = lane >> 2, tig = lane & 3;

    // triangular decode: blockIdx.x -> (bx >= by)
    int t = blockIdx.x;
    int a = (int)((sqrtf(8.0f * (float)t + 1.0f) - 1.0f) * 0.5f);
    while ((a + 1) * (a + 2) / 2 <= t) a++;
    while (a * (a + 1) / 2 > t) a--;
    const int bx = a;
    const int by = t - a * (a + 1) / 2;
    const int rowTile = by * TS;
    const int colTile = bx * TS;

    const uint32_t smbase = smem_u32(smh);

    // ldmatrix per-lane address components (half-element offsets)
    const uint32_t aRow = (uint32_t)(warpM * 32 + (lane & 15));
    const uint32_t aK   = (uint32_t)((lane >> 4) * 8);
    const uint32_t bRow = (uint32_t)(warpN * 64 + ((lane >> 4) & 1) * 8 + (lane & 7));
    const uint32_t bK   = (uint32_t)(((lane >> 3) & 1) * 8);

    float c[2][8][4];
#pragma unroll
    for (int i = 0; i < 2; i++)
#pragma unroll
        for (int j = 0; j < 8; j++)
#pragma unroll
            for (int q = 0; q < 4; q++) c[i][j][q] = 0.f;

    // stage loader: 4 tiles (AH, AL, BH, BL), each 128 rows x 64 halves
    auto issue_stage = [&](int stage, int k0) {
        const __half* gsrc[4] = {g_hi, g_lo, g_hi, g_lo};
        const int    rbase[4] = {rowTile, rowTile, colTile, colTile};
#pragma unroll
        for (int tIdx = 0; tIdx < 4; tIdx++) {
            const __half* src = gsrc[tIdx];
            uint32_t dstBase = smbase + (uint32_t)(stage * STAGE_H + tIdx * TILE_H) * 2u;
#pragma unroll
            for (int q = 0; q < 4; q++) {
                int seg = tid + q * 256;            // 0..1023
                int m = seg >> 3, s = seg & 7;      // row, 16B segment (8 halves)
                uint32_t d = dstBase + (uint32_t)(m * LDKH + s * 8) * 2u;
                const __half* g = src + (size_t)(rbase[tIdx] + m) * D_DIM + k0 + s * 8;
                CP_ASYNC_CG(d, g);
            }
        }
        CP_COMMIT();
    };

    issue_stage(0, 0);

    for (int it = 0; it < NSTAGE; it++) {
        if (it + 1 < NSTAGE) {
            issue_stage((it + 1) & 1, (it + 1) * KC);
            CP_WAIT(1);
        } else {
            CP_WAIT(0);
        }
        __syncthreads();

        const uint32_t AHs = smbase + (uint32_t)((it & 1) * STAGE_H) * 2u;
        const uint32_t ALs = AHs + (uint32_t)TILE_H * 2u;
        const uint32_t BHs = AHs + (uint32_t)(2 * TILE_H) * 2u;
        const uint32_t BLs = AHs + (uint32_t)(3 * TILE_H) * 2u;

#pragma unroll
        for (int kk = 0; kk < 4; kk++) {           // four k16 steps per stage
            const uint32_t kb = (uint32_t)(kk * 16);
            uint32_t ah[2][4], al[2][4], bh[8][2], bl[8][2];
#pragma unroll
            for (int tm = 0; tm < 2; tm++) {
                uint32_t offA = ((aRow + tm * 16u) * LDKH + kb + aK) * 2u;
                LDSM_X4(ah[tm][0], ah[tm][1], ah[tm][2], ah[tm][3], AHs + offA);
                LDSM_X4(al[tm][0], al[tm][1], al[tm][2], al[tm][3], ALs + offA);
            }
#pragma unroll
            for (int tp = 0; tp < 4; tp++) {
                uint32_t offB = ((bRow + tp * 16u) * LDKH + kb + bK) * 2u;
                LDSM_X4(bh[2 * tp][0], bh[2 * tp][1], bh[2 * tp + 1][0], bh[2 * tp + 1][1],
                        BHs + offB);
                LDSM_X4(bl[2 * tp][0], bl[2 * tp][1], bl[2 * tp + 1][0], bl[2 * tp + 1][1],
                        BLs + offB);
            }
#pragma unroll
            for (int tm = 0; tm < 2; tm++)
#pragma unroll
                for (int tn = 0; tn < 8; tn++) {
                    MMA_F16(c[tm][tn], ah[tm], bh[tn]);
                    MMA_F16(c[tm][tn], ah[tm], bl[tn]);
                    MMA_F16(c[tm][tn], al[tm], bh[tn]);
                }
        }
        __syncthreads();
    }

    // Epilogue: d = sqrt(max(sq_r + sq_c - 2*dot, 0)); stores + min tracking
    float rmin[2][2];                  // [tm][0]=row r0, [tm][1]=row r0+8
    float cmin[8][2];                  // [tn][0]=col c0, [tn][1]=col c0+1
#pragma unroll
    for (int i = 0; i < 2; i++) { rmin[i][0] = FLT_MAX; rmin[i][1] = FLT_MAX; }
#pragma unroll
    for (int j = 0; j < 8; j++) { cmin[j][0] = FLT_MAX; cmin[j][1] = FLT_MAX; }

#pragma unroll
    for (int tm = 0; tm < 2; tm++) {
        int r0 = rowTile + warpM * 32 + tm * 16 + gID;
        float sqr0 = g_sq[r0], sqr1 = g_sq[r0 + 8];
#pragma unroll
        for (int tn = 0; tn < 8; tn++) {
            int c0 = colTile + warpN * 64 + tn * 8 + 2 * tig;
            float sqc0 = g_sq[c0], sqc1 = g_sq[c0 + 1];
            float* C = c[tm][tn];
            float v00 = sqrtf(fmaxf(sqr0 + sqc0 - 2.f * C[0], 0.f));
            float v01 = sqrtf(fmaxf(sqr0 + sqc1 - 2.f * C[1], 0.f));
            float v10 = sqrtf(fmaxf(sqr1 + sqc0 - 2.f * C[2], 0.f));
            float v11 = sqrtf(fmaxf(sqr1 + sqc1 - 2.f * C[3], 0.f));
            *reinterpret_cast<float2*>(&g_dist[(size_t)r0 * T_DIM + c0]) =
                make_float2(v00, v01);
            *reinterpret_cast<float2*>(&g_dist[(size_t)(r0 + 8) * T_DIM + c0]) =
                make_float2(v10, v11);
            if (bx != by) {
                g_dist[(size_t)c0 * T_DIM + r0]           = v00;
                g_dist[(size_t)c0 * T_DIM + r0 + 8]       = v10;
                g_dist[(size_t)(c0 + 1) * T_DIM + r0]     = v01;
                g_dist[(size_t)(c0 + 1) * T_DIM + r0 + 8] = v11;
            }
            rmin[tm][0] = fminf(rmin[tm][0], fminf(v00, v01));
            rmin[tm][1] = fminf(rmin[tm][1], fminf(v10, v11));
            cmin[tn][0] = fminf(cmin[tn][0], fminf(v00, v10));
            cmin[tn][1] = fminf(cmin[tn][1], fminf(v01, v11));
        }
    }

    // block-min combine (reuse stage smem; prior __syncthreads ended reads)
    float* srow = reinterpret_cast<float*>(smh);            // [128][2]
    float* scol = srow + 256;                               // [128][4]
#pragma unroll
    for (int tm = 0; tm < 2; tm++)
#pragma unroll
        for (int s = 0; s < 2; s++) {
            float m = rmin[tm][s];
            m = fminf(m, __shfl_xor_sync(0xffffffffu, m, 1));
            m = fminf(m, __shfl_xor_sync(0xffffffffu, m, 2));
            if (tig == 0) {
                int r = warpM * 32 + tm * 16 + s * 8 + gID;
                srow[r * 2 + warpN] = m;
            }
        }
#pragma unroll
    for (int tn = 0; tn < 8; tn++)
#pragma unroll
        for (int s = 0; s < 2; s++) {
            float m = cmin[tn][s];
            m = fminf(m, __shfl_xor_sync(0xffffffffu, m, 4));
            m = fminf(m, __shfl_xor_sync(0xffffffffu, m, 8));
            m = fminf(m, __shfl_xor_sync(0xffffffffu, m, 16));
            if (gID == 0) {
                int cl = warpN * 64 + tn * 8 + 2 * tig + s;
                scol[cl * 4 + warpM] = m;
            }
        }
    __syncthreads();
    if (tid < 128) {
        g_bmin[(size_t)(rowTile + tid) * NTILE + bx] = fminf(srow[tid * 2], srow[tid * 2 + 1]);
    } else if (bx != by) {
        int cl = tid - 128;
        float m = fminf(fminf(scol[cl * 4], scol[cl * 4 + 1]),
                        fminf(scol[cl * 4 + 2], scol[cl * 4 + 3]));
        g_bmin[(size_t)(colTile + cl) * NTILE + by] = m;
    }
}

// ---------------------------------------------------------------------------
// 4) Slim top-k: tau from precomputed block-mins, exact scan of the ~5
//    surviving 128-blocks only. One warp per row.
// ---------------------------------------------------------------------------
__global__ __launch_bounds__(128) void topk_kernel() {
    __shared__ float sb[4][64];
    __shared__ float sd[4][32][5];
    __shared__ int   si[4][32][5];
    const int wid = threadIdx.x >> 5, lane = threadIdx.x & 31;
    const int row = blockIdx.x * 4 + wid;

    const float* bm = g_bmin + (size_t)row * NTILE;
    sb[wid][lane]      = bm[lane];
    sb[wid][lane + 32] = bm[lane + 32];
    __syncwarp();

    // tau = 5th smallest block-min (redundant per lane; smem broadcast reads)
    float t5[5] = {FLT_MAX, FLT_MAX, FLT_MAX, FLT_MAX, FLT_MAX};
#pragma unroll
    for (int b = 0; b < 64; b++) {
        float x = sb[wid][b];
        if (x < t5[4]) {
            t5[4] = x;
#pragma unroll
            for (int p = 4; p > 0; p--)
                if (t5[p] < t5[p - 1]) { float tt = t5[p]; t5[p] = t5[p - 1]; t5[p - 1] = tt; }
        }
    }
    const float tau = t5[4];

    // exact scan of surviving blocks
    const float* drow = g_dist + (size_t)row * T_DIM;
    float d5[5]; int i5[5];
#pragma unroll
    for (int r = 0; r < 5; r++) { d5[r] = FLT_MAX; i5[r] = 0x7fffffff; }
    for (int b = 0; b < 64; b++) {
        if (sb[wid][b] <= tau) {
            float4 v = reinterpret_cast<const float4*>(drow + b * 128)[lane];
            int jb = b * 128 + lane * 4;
            if (v.x <= d5[4]) insert5(v.x, jb,     d5, i5);
            if (v.y <= d5[4]) insert5(v.y, jb + 1, d5, i5);
            if (v.z <= d5[4]) insert5(v.z, jb + 2, d5, i5);
            if (v.w <= d5[4]) insert5(v.w, jb + 3, d5, i5);
        }
    }
#pragma unroll
    for (int r = 0; r < 5; r++) { sd[wid][lane][r] = d5[r]; si[wid][lane][r] = i5[r]; }
    __syncwarp();

    if (lane == 0) {
        for (int t = 1; t < 32; t++)
#pragma unroll
            for (int r = 0; r < 5; r++)
                insert5(sd[wid][t][r], si[wid][t][r], d5, i5);
        // rank 0 is self; keep ranks 1..4
#pragma unroll
        for (int r = 0; r < 4; r++) g_nb[row * 4 + r] = i5[r + 1];
    }
}

// ---------------------------------------------------------------------------
// 5) Interpolate
// ---------------------------------------------------------------------------
__global__ __launch_bounds__(128) void synth_kernel(const float* __restrict__ X,
                                                    const float* __restrict__ gaps,
                                                    const int* __restrict__ choice,
                                                    float* __restrict__ out) {
    int s = blockIdx.x;
    int i = s >> 2;
    int c = choice[s];
    int sel = g_nb[i * 4 + c];
    float g = gaps[s];

    const float4* base = reinterpret_cast<const float4*>(X + (size_t)i * D_DIM);
    const float4* nb   = reinterpret_cast<const float4*>(X + (size_t)sel * D_DIM);
    float4* o = reinterpret_cast<float4*>(out + (size_t)s * D_DIM);

    int t = threadIdx.x;
    float4 b = base[t], v = nb[t];
    float4 r;
    r.x = fmaf(g, v.x - b.x, b.x);
    r.y = fmaf(g, v.y - b.y, b.y);
    r.z = fmaf(g, v.z - b.z, b.z);
    r.w = fmaf(g, v.w - b.w, b.w);
    o[t] = r;
}

// ---------------------------------------------------------------------------
extern "C" void kernel_launch(void* const* d_in, const int* in_sizes, int n_in,
                              void* d_out, int out_size) {
    const float* X      = (const float*)d_in[0];   // [8192, 512]
    const float* gaps   = (const float*)d_in[1];   // [8192, 4]
    const int*   choice = (const int*)d_in[2];     // [8192, 4]
    float* out = (float*)d_out;                    // [32768, 512]

    const int smem_bytes = 2 * STAGE_H * 2;        // 147456 B
    cudaFuncSetAttribute(dist_mma_kernel,
                         cudaFuncAttributeMaxDynamicSharedMemorySize, smem_bytes);

    sq_kernel<<<(T_DIM * 32 + 255) / 256, 256>>>(X);
    split_kernel<<<(T_DIM * D_DIM / 4) / 256, 256>>>(X);
    dist_mma_kernel<<<NTILE * (NTILE + 1) / 2, 256, smem_bytes>>>();
    topk_kernel<<<T_DIM / 4, 128>>>();
    synth_kernel<<<T_DIM * N_SYN, 128>>>(X, gaps, choice, out);
}

// round 17
// speedup vs baseline: 1.8203x; 1.1274x over previous
#include <cuda_runtime.h>
#include <cuda_fp16.h>
#include <math.h>
#include <float.h>
#include <stdint.h>

#define T_DIM 8192
#define D_DIM 512
#define N_SYN 4
#define NTILE 64                  // 8192 / 128 blocks per row
#define TS 128                    // CTA tile M=N
#define KC 32                     // k elems (halves) per smem stage
#define NSTAGE (D_DIM / KC)       // 16
#define LDKH 40                   // padded stride in halves (80B = 16*5, conflict-free LDSM)
#define TILE_H (TS * LDKH)        // halves per tile (5120)
#define STAGE_H (4 * TILE_H)      // AH AL BH BL (20480 halves = 40960 B)

// ---------------------------------------------------------------------------
// Device-global scratch
// ---------------------------------------------------------------------------
__device__ float g_sq[T_DIM];
__device__ float g_dist[(size_t)T_DIM * T_DIM];   // 256 MB
__device__ float g_bmin[(size_t)T_DIM * NTILE];   // 2 MB per-(row, 128-block) min
__device__ int   g_nb[T_DIM * 4];
__device__ __half g_hi[(size_t)T_DIM * D_DIM];    // 8 MB
__device__ __half g_lo[(size_t)T_DIM * D_DIM];    // 8 MB

// ---------------------------------------------------------------------------
// PTX helpers (baseline sm_80+ -> legal on compute_103)
// ---------------------------------------------------------------------------
__device__ __forceinline__ uint32_t smem_u32(const void* p) {
    uint32_t a;
    asm("{ .reg .u64 t; cvta.to.shared.u64 t, %1; cvt.u32.u64 %0, t; }" : "=r"(a) : "l"(p));
    return a;
}
#define CP_ASYNC_CG(dst_u32, src_ptr) \
    asm volatile("cp.async.cg.shared.global [%0], [%1], 16;" :: "r"(dst_u32), "l"(src_ptr))
#define CP_COMMIT() asm volatile("cp.async.commit_group;" ::: "memory")
#define CP_WAIT(n)  asm volatile("cp.async.wait_group %0;" :: "n"(n) : "memory")

#define MMA_F16(Cp, a, b) \
    asm volatile("mma.sync.aligned.m16n8k16.row.col.f32.f16.f16.f32 " \
        "{%0,%1,%2,%3}, {%4,%5,%6,%7}, {%8,%9}, {%0,%1,%2,%3};" \
        : "+f"((Cp)[0]), "+f"((Cp)[1]), "+f"((Cp)[2]), "+f"((Cp)[3]) \
        : "r"((a)[0]), "r"((a)[1]), "r"((a)[2]), "r"((a)[3]), \
          "r"((b)[0]), "r"((b)[1]))

#define LDSM_X4(r0, r1, r2, r3, addr) \
    asm volatile("ldmatrix.sync.aligned.m8n8.x4.shared.b16 {%0,%1,%2,%3}, [%4];" \
        : "=r"(r0), "=r"(r1), "=r"(r2), "=r"(r3) : "r"(addr))

// ---------------------------------------------------------------------------
// exact top-5 insert, jax.lax.top_k tie semantics (value, then lower index)
// ---------------------------------------------------------------------------
__device__ __forceinline__ bool kless(float d1, int i1, float d2, int i2) {
    return (d1 < d2) || (d1 == d2 && i1 < i2);
}
__device__ __forceinline__ void insert5(float d, int j, float (&d5)[5], int (&i5)[5]) {
    if (kless(d, j, d5[4], i5[4])) {
        d5[4] = d; i5[4] = j;
#pragma unroll
        for (int p = 4; p > 0; p--) {
            if (kless(d5[p], i5[p], d5[p - 1], i5[p - 1])) {
                float td = d5[p]; d5[p] = d5[p - 1]; d5[p - 1] = td;
                int   ti = i5[p]; i5[p] = i5[p - 1]; i5[p - 1] = ti;
            }
        }
    }
}

// ---------------------------------------------------------------------------
// 1) Row squared norms (fp32): one warp per row
// ---------------------------------------------------------------------------
__global__ void sq_kernel(const float* __restrict__ X) {
    int warp = (blockIdx.x * blockDim.x + threadIdx.x) >> 5;
    int lane = threadIdx.x & 31;
    if (warp >= T_DIM) return;
    const float4* xr = reinterpret_cast<const float4*>(X + (size_t)warp * D_DIM);
    float s = 0.f;
#pragma unroll
    for (int c = 0; c < 4; c++) {
        float4 v = xr[lane + c * 32];
        s += v.x * v.x + v.y * v.y + v.z * v.z + v.w * v.w;
    }
#pragma unroll
    for (int o = 16; o > 0; o >>= 1) s += __shfl_down_sync(0xffffffffu, s, o);
    if (lane == 0) g_sq[warp] = s;
}

// ---------------------------------------------------------------------------
// 2) fp16 2-way split: x = hi + lo + r, |r| <= 2^-22 |x|
// ---------------------------------------------------------------------------
__global__ void split_kernel(const float* __restrict__ X) {
    int i = blockIdx.x * blockDim.x + threadIdx.x;   // over T*D/4
    float4 v = reinterpret_cast<const float4*>(X)[i];
    float xs[4] = {v.x, v.y, v.z, v.w};
    unsigned short h[4], l[4];
#pragma unroll
    for (int c = 0; c < 4; c++) {
        __half hh = __float2half_rn(xs[c]);
        float r = xs[c] - __half2float(hh);
        __half ll = __float2half_rn(r);
        h[c] = __half_as_ushort(hh);
        l[c] = __half_as_ushort(ll);
    }
    reinterpret_cast<ushort4*>(g_hi)[i] = make_ushort4(h[0], h[1], h[2], h[3]);
    reinterpret_cast<ushort4*>(g_lo)[i] = make_ushort4(l[0], l[1], l[2], l[3]);
}

// ---------------------------------------------------------------------------
// 3) Triangular dist GEMM (mma.sync fp16, dot = hh + hl + lh), 2 CTAs/SM.
//    KC=32 halves/stage, stride 40 halves (80B, LDSM conflict-free).
//    Stage = 4 tiles x 128 rows x 4 16B-segments = 2048 segs -> 8/thread.
// ---------------------------------------------------------------------------
__global__ __launch_bounds__(256, 2) void dist_mma_kernel() {
    extern __shared__ __align__(16) __half smh[];
    const int tid = threadIdx.x;
    const int lane = tid & 31, wid = tid >> 5;
    const int warpM = wid & 3;        // m offset *32
    const int warpN = wid >> 2;       // n offset *64
    const int gID = lane >> 2, tig = lane & 3;

    // triangular decode: blockIdx.x -> (bx >= by)
    int t = blockIdx.x;
    int a = (int)((sqrtf(8.0f * (float)t + 1.0f) - 1.0f) * 0.5f);
    while ((a + 1) * (a + 2) / 2 <= t) a++;
    while (a * (a + 1) / 2 > t) a--;
    const int bx = a;
    const int by = t - a * (a + 1) / 2;
    const int rowTile = by * TS;
    const int colTile = bx * TS;

    const uint32_t smbase = smem_u32(smh);

    // ldmatrix per-lane address components (half-element offsets)
    const uint32_t aRow = (uint32_t)(warpM * 32 + (lane & 15));
    const uint32_t aK   = (uint32_t)((lane >> 4) * 8);
    const uint32_t bRow = (uint32_t)(warpN * 64 + ((lane >> 4) & 1) * 8 + (lane & 7));
    const uint32_t bK   = (uint32_t)(((lane >> 3) & 1) * 8);

    float c[2][8][4];
#pragma unroll
    for (int i = 0; i < 2; i++)
#pragma unroll
        for (int j = 0; j < 8; j++)
#pragma unroll
            for (int q = 0; q < 4; q++) c[i][j][q] = 0.f;

    // stage loader: 2048 16B-segments -> 8 cp.async per thread
    auto issue_stage = [&](int stage, int k0) {
        const __half* gsrc[4] = {g_hi, g_lo, g_hi, g_lo};
        const int    rbase[4] = {rowTile, rowTile, colTile, colTile};
#pragma unroll
        for (int q = 0; q < 8; q++) {
            int seg = tid + q * 256;                // 0..2047
            int tIdx = seg >> 9;                    // tile (512 segs per tile)
            int m = (seg & 511) >> 2, s = seg & 3;  // row, 16B segment (8 halves)
            uint32_t d = smbase +
                (uint32_t)(stage * STAGE_H + tIdx * TILE_H + m * LDKH + s * 8) * 2u;
            const __half* g = gsrc[tIdx] + (size_t)(rbase[tIdx] + m) * D_DIM + k0 + s * 8;
            CP_ASYNC_CG(d, g);
        }
        CP_COMMIT();
    };

    issue_stage(0, 0);

    for (int it = 0; it < NSTAGE; it++) {
        if (it + 1 < NSTAGE) {
            issue_stage((it + 1) & 1, (it + 1) * KC);
            CP_WAIT(1);
        } else {
            CP_WAIT(0);
        }
        __syncthreads();

        const uint32_t AHs = smbase + (uint32_t)((it & 1) * STAGE_H) * 2u;
        const uint32_t ALs = AHs + (uint32_t)TILE_H * 2u;
        const uint32_t BHs = AHs + (uint32_t)(2 * TILE_H) * 2u;
        const uint32_t BLs = AHs + (uint32_t)(3 * TILE_H) * 2u;

#pragma unroll
        for (int kk = 0; kk < 2; kk++) {           // two k16 steps per stage
            const uint32_t kb = (uint32_t)(kk * 16);
            uint32_t ah[2][4], al[2][4];
#pragma unroll
            for (int tm = 0; tm < 2; tm++) {
                uint32_t offA = ((aRow + tm * 16u) * LDKH + kb + aK) * 2u;
                LDSM_X4(ah[tm][0], ah[tm][1], ah[tm][2], ah[tm][3], AHs + offA);
                LDSM_X4(al[tm][0], al[tm][1], al[tm][2], al[tm][3], ALs + offA);
            }
#pragma unroll
            for (int tp = 0; tp < 4; tp++) {       // B loaded per-pair (low regs)
                uint32_t bh[2][2], bl[2][2];
                uint32_t offB = ((bRow + tp * 16u) * LDKH + kb + bK) * 2u;
                LDSM_X4(bh[0][0], bh[0][1], bh[1][0], bh[1][1], BHs + offB);
                LDSM_X4(bl[0][0], bl[0][1], bl[1][0], bl[1][1], BLs + offB);
#pragma unroll
                for (int tm = 0; tm < 2; tm++)
#pragma unroll
                    for (int q = 0; q < 2; q++) {
                        int tn = 2 * tp + q;
                        MMA_F16(c[tm][tn], ah[tm], bh[q]);
                        MMA_F16(c[tm][tn], ah[tm], bl[q]);
                        MMA_F16(c[tm][tn], al[tm], bh[q]);
                    }
            }
        }
        __syncthreads();
    }

    // Epilogue: d = sqrt(max(sq_r + sq_c - 2*dot, 0)); stores + min tracking
    float rmin[2][2];
    float cmin[8][2];
#pragma unroll
    for (int i = 0; i < 2; i++) { rmin[i][0] = FLT_MAX; rmin[i][1] = FLT_MAX; }
#pragma unroll
    for (int j = 0; j < 8; j++) { cmin[j][0] = FLT_MAX; cmin[j][1] = FLT_MAX; }

#pragma unroll
    for (int tm = 0; tm < 2; tm++) {
        int r0 = rowTile + warpM * 32 + tm * 16 + gID;
        float sqr0 = g_sq[r0], sqr1 = g_sq[r0 + 8];
#pragma unroll
        for (int tn = 0; tn < 8; tn++) {
            int c0 = colTile + warpN * 64 + tn * 8 + 2 * tig;
            float sqc0 = g_sq[c0], sqc1 = g_sq[c0 + 1];
            float* C = c[tm][tn];
            float v00 = sqrtf(fmaxf(sqr0 + sqc0 - 2.f * C[0], 0.f));
            float v01 = sqrtf(fmaxf(sqr0 + sqc1 - 2.f * C[1], 0.f));
            float v10 = sqrtf(fmaxf(sqr1 + sqc0 - 2.f * C[2], 0.f));
            float v11 = sqrtf(fmaxf(sqr1 + sqc1 - 2.f * C[3], 0.f));
            *reinterpret_cast<float2*>(&g_dist[(size_t)r0 * T_DIM + c0]) =
                make_float2(v00, v01);
            *reinterpret_cast<float2*>(&g_dist[(size_t)(r0 + 8) * T_DIM + c0]) =
                make_float2(v10, v11);
            if (bx != by) {
                g_dist[(size_t)c0 * T_DIM + r0]           = v00;
                g_dist[(size_t)c0 * T_DIM + r0 + 8]       = v10;
                g_dist[(size_t)(c0 + 1) * T_DIM + r0]     = v01;
                g_dist[(size_t)(c0 + 1) * T_DIM + r0 + 8] = v11;
            }
            rmin[tm][0] = fminf(rmin[tm][0], fminf(v00, v01));
            rmin[tm][1] = fminf(rmin[tm][1], fminf(v10, v11));
            cmin[tn][0] = fminf(cmin[tn][0], fminf(v00, v10));
            cmin[tn][1] = fminf(cmin[tn][1], fminf(v01, v11));
        }
    }

    // block-min combine (reuse stage smem; prior __syncthreads ended reads)
    float* srow = reinterpret_cast<float*>(smh);            // [128][2]
    float* scol = srow + 256;                               // [128][4]
#pragma unroll
    for (int tm = 0; tm < 2; tm++)
#pragma unroll
        for (int s = 0; s < 2; s++) {
            float m = rmin[tm][s];
            m = fminf(m, __shfl_xor_sync(0xffffffffu, m, 1));
            m = fminf(m, __shfl_xor_sync(0xffffffffu, m, 2));
            if (tig == 0) {
                int r = warpM * 32 + tm * 16 + s * 8 + gID;
                srow[r * 2 + warpN] = m;
            }
        }
#pragma unroll
    for (int tn = 0; tn < 8; tn++)
#pragma unroll
        for (int s = 0; s < 2; s++) {
            float m = cmin[tn][s];
            m = fminf(m, __shfl_xor_sync(0xffffffffu, m, 4));
            m = fminf(m, __shfl_xor_sync(0xffffffffu, m, 8));
            m = fminf(m, __shfl_xor_sync(0xffffffffu, m, 16));
            if (gID == 0) {
                int cl = warpN * 64 + tn * 8 + 2 * tig + s;
                scol[cl * 4 + warpM] = m;
            }
        }
    __syncthreads();
    if (tid < 128) {
        g_bmin[(size_t)(rowTile + tid) * NTILE + bx] = fminf(srow[tid * 2], srow[tid * 2 + 1]);
    } else if (bx != by) {
        int cl = tid - 128;
        float m = fminf(fminf(scol[cl * 4], scol[cl * 4 + 1]),
                        fminf(scol[cl * 4 + 2], scol[cl * 4 + 3]));
        g_bmin[(size_t)(colTile + cl) * NTILE + by] = m;
    }
}

// ---------------------------------------------------------------------------
// 4) Slim top-k: tau from precomputed block-mins, exact scan of the ~5
//    surviving 128-blocks only. One warp per row, 8 warps/CTA.
// ---------------------------------------------------------------------------
__global__ __launch_bounds__(256) void topk_kernel() {
    __shared__ float sb[8][64];
    __shared__ float sd[8][32][5];
    __shared__ int   si[8][32][5];
    const int wid = threadIdx.x >> 5, lane = threadIdx.x & 31;
    const int row = blockIdx.x * 8 + wid;

    const float* bm = g_bmin + (size_t)row * NTILE;
    sb[wid][lane]      = bm[lane];
    sb[wid][lane + 32] = bm[lane + 32];
    __syncwarp();

    // tau = 5th smallest block-min (redundant per lane; smem broadcast reads)
    float t5[5] = {FLT_MAX, FLT_MAX, FLT_MAX, FLT_MAX, FLT_MAX};
#pragma unroll
    for (int b = 0; b < 64; b++) {
        float x = sb[wid][b];
        if (x < t5[4]) {
            t5[4] = x;
#pragma unroll
            for (int p = 4; p > 0; p--)
                if (t5[p] < t5[p - 1]) { float tt = t5[p]; t5[p] = t5[p - 1]; t5[p - 1] = tt; }
        }
    }
    const float tau = t5[4];

    // exact scan of surviving blocks
    const float* drow = g_dist + (size_t)row * T_DIM;
    float d5[5]; int i5[5];
#pragma unroll
    for (int r = 0; r < 5; r++) { d5[r] = FLT_MAX; i5[r] = 0x7fffffff; }
    for (int b = 0; b < 64; b++) {
        if (sb[wid][b] <= tau) {
            float4 v = reinterpret_cast<const float4*>(drow + b * 128)[lane];
            int jb = b * 128 + lane * 4;
            if (v.x <= d5[4]) insert5(v.x, jb,     d5, i5);
            if (v.y <= d5[4]) insert5(v.y, jb + 1, d5, i5);
            if (v.z <= d5[4]) insert5(v.z, jb + 2, d5, i5);
            if (v.w <= d5[4]) insert5(v.w, jb + 3, d5, i5);
        }
    }
#pragma unroll
    for (int r = 0; r < 5; r++) { sd[wid][lane][r] = d5[r]; si[wid][lane][r] = i5[r]; }
    __syncwarp();

    if (lane == 0) {
        for (int t = 1; t < 32; t++)
#pragma unroll
            for (int r = 0; r < 5; r++)
                insert5(sd[wid][t][r], si[wid][t][r], d5, i5);
        // rank 0 is self; keep ranks 1..4
#pragma unroll
        for (int r = 0; r < 4; r++) g_nb[row * 4 + r] = i5[r + 1];
    }
}

// ---------------------------------------------------------------------------
// 5) Interpolate
// ---------------------------------------------------------------------------
__global__ __launch_bounds__(128) void synth_kernel(const float* __restrict__ X,
                                                    const float* __restrict__ gaps,
                                                    const int* __restrict__ choice,
                                                    float* __restrict__ out) {
    int s = blockIdx.x;
    int i = s >> 2;
    int c = choice[s];
    int sel = g_nb[i * 4 + c];
    float g = gaps[s];

    const float4* base = reinterpret_cast<const float4*>(X + (size_t)i * D_DIM);
    const float4* nb   = reinterpret_cast<const float4*>(X + (size_t)sel * D_DIM);
    float4* o = reinterpret_cast<float4*>(out + (size_t)s * D_DIM);

    int t = threadIdx.x;
    float4 b = base[t], v = nb[t];
    float4 r;
    r.x = fmaf(g, v.x - b.x, b.x);
    r.y = fmaf(g, v.y - b.y, b.y);
    r.z = fmaf(g, v.z - b.z, b.z);
    r.w = fmaf(g, v.w - b.w, b.w);
    o[t] = r;
}

// ---------------------------------------------------------------------------
extern "C" void kernel_launch(void* const* d_in, const int* in_sizes, int n_in,
                              void* d_out, int out_size) {
    const float* X      = (const float*)d_in[0];   // [8192, 512]
    const float* gaps   = (const float*)d_in[1];   // [8192, 4]
    const int*   choice = (const int*)d_in[2];     // [8192, 4]
    float* out = (float*)d_out;                    // [32768, 512]

    const int smem_bytes = 2 * STAGE_H * 2;        // 81920 B -> 2 CTAs/SM
    cudaFuncSetAttribute(dist_mma_kernel,
                         cudaFuncAttributeMaxDynamicSharedMemorySize, smem_bytes);

    sq_kernel<<<(T_DIM * 32 + 255) / 256, 256>>>(X);
    split_kernel<<<(T_DIM * D_DIM / 4) / 256, 256>>>(X);
    dist_mma_kernel<<<NTILE * (NTILE + 1) / 2, 256, smem_bytes>>>();
    topk_kernel<<<T_DIM / 8, 256>>>();
    synth_kernel<<<T_DIM * N_SYN, 128>>>(X, gaps, choice, out);
}